// round 7
// baseline (speedup 1.0000x reference)
#include <cuda_runtime.h>

#define B_   2
#define T_   2048
#define C_   1024
#define NH_  16
#define HD_  64
#define NTOK 4096   // B_*T_

// Scratch (allocation-free: __device__ globals)
__device__ float g_Q[B_ * NH_ * T_ * HD_];   // [b][h][t][d]
__device__ float g_K[B_ * NH_ * T_ * HD_];
__device__ float g_V[B_ * NH_ * T_ * HD_];
__device__ float g_O[NTOK * C_];             // attention out, [b*T+t][h*64+d]

// ---------------------------------------------------------------------------
// GEMM: C[M,N] = A[M,K] @ W[N,K]^T   (K = 1024, tiles 128x128x8, 8x8/thread)
// MODE 0: A = x, scatter output into g_Q/g_K/g_V ([B,H,T,D])
// MODE 1: A = g_O, write Cout row-major (final output)
// ---------------------------------------------------------------------------
template <int MODE>
__global__ void __launch_bounds__(256, 2)
gemm_kernel(const float* __restrict__ A_in, const float* __restrict__ W,
            float* __restrict__ Cout)
{
    __shared__ float As[8][128];
    __shared__ float Bs[8][128];
    const float* A = (MODE == 1) ? (const float*)g_O : A_in;

    const int tid = threadIdx.x;
    const int tx = tid & 15;
    const int ty = tid >> 4;
    const int m0 = blockIdx.y * 128;
    const int n0 = blockIdx.x * 128;

    float acc[8][8];
#pragma unroll
    for (int i = 0; i < 8; i++)
#pragma unroll
        for (int j = 0; j < 8; j++) acc[i][j] = 0.f;

    const int lr = tid >> 1;          // 0..127
    const int lc = (tid & 1) * 4;     // 0 or 4
    const float* Ag = A + (m0 + lr) * 1024 + lc;
    const float* Wg = W + (n0 + lr) * 1024 + lc;

    for (int k0 = 0; k0 < 1024; k0 += 8) {
        float4 a = *(const float4*)(Ag + k0);
        float4 b = *(const float4*)(Wg + k0);
        __syncthreads();
        As[lc + 0][lr] = a.x; As[lc + 1][lr] = a.y;
        As[lc + 2][lr] = a.z; As[lc + 3][lr] = a.w;
        Bs[lc + 0][lr] = b.x; Bs[lc + 1][lr] = b.y;
        Bs[lc + 2][lr] = b.z; Bs[lc + 3][lr] = b.w;
        __syncthreads();
#pragma unroll
        for (int kk = 0; kk < 8; kk++) {
            float af[8], bf[8];
            *(float4*)(af)     = *(const float4*)&As[kk][ty * 8];
            *(float4*)(af + 4) = *(const float4*)&As[kk][ty * 8 + 4];
            *(float4*)(bf)     = *(const float4*)&Bs[kk][tx * 8];
            *(float4*)(bf + 4) = *(const float4*)&Bs[kk][tx * 8 + 4];
#pragma unroll
            for (int i = 0; i < 8; i++)
#pragma unroll
                for (int j = 0; j < 8; j++)
                    acc[i][j] = fmaf(af[i], bf[j], acc[i][j]);
        }
    }

    if (MODE == 0) {
        // scatter into Q/K/V [b][h][t][d]; column block lies in one head (64|8)
        const int ncol = n0 + tx * 8;
        const int part = ncol >> 10;            // 0=Q 1=K 2=V
        const int h    = (ncol >> 6) & 15;
        const int d0   = ncol & 63;
        float* dst = (part == 0) ? g_Q : (part == 1) ? g_K : g_V;
#pragma unroll
        for (int i = 0; i < 8; i++) {
            const int m = m0 + ty * 8 + i;
            const int b = m >> 11;
            const int t = m & 2047;
            float* p = dst + (((b * NH_ + h) * T_) + t) * HD_ + d0;
            *(float4*)p       = make_float4(acc[i][0], acc[i][1], acc[i][2], acc[i][3]);
            *(float4*)(p + 4) = make_float4(acc[i][4], acc[i][5], acc[i][6], acc[i][7]);
        }
    } else {
#pragma unroll
        for (int i = 0; i < 8; i++) {
            float* p = Cout + (m0 + ty * 8 + i) * 1024 + n0 + tx * 8;
            *(float4*)p       = make_float4(acc[i][0], acc[i][1], acc[i][2], acc[i][3]);
            *(float4*)(p + 4) = make_float4(acc[i][4], acc[i][5], acc[i][6], acc[i][7]);
        }
    }
}

// ---------------------------------------------------------------------------
// RoPE (in place on g_Q/g_K); folds softmax scale 1/sqrt(64) into Q.
// One thread per (b,h,t,d<32) rotation pair, handles both Q and K.
// ---------------------------------------------------------------------------
__global__ void rope_kernel(const float* __restrict__ cosb,
                            const float* __restrict__ sinb)
{
    const int idx = blockIdx.x * blockDim.x + threadIdx.x;
    if (idx >= B_ * NH_ * T_ * 32) return;
    const int d  = idx & 31;
    const int t  = (idx >> 5) & 2047;
    const int bh = idx >> 16;                  // /(2048*32)
    const float c = cosb[t * 32 + d];
    const float s = sinb[t * 32 + d];
    const int base = (bh * T_ + t) * HD_ + d;

    const float q1 = g_Q[base], q2 = g_Q[base + 32];
    g_Q[base]      = (q1 * c - q2 * s) * 0.125f;
    g_Q[base + 32] = (q1 * s + q2 * c) * 0.125f;

    const float k1 = g_K[base], k2 = g_K[base + 32];
    g_K[base]      = k1 * c - k2 * s;
    g_K[base + 32] = k1 * s + k2 * c;
}

// ---------------------------------------------------------------------------
// Flash attention, fp32, causal. Tile: 128 q x 128 k, 256 threads (16x16),
// 8x8 S accum per thread, 8x4 O accum per thread. Q/K stored d-major in smem
// (GEMM-style conflict-free fragment reads); P row-major (float4 writes,
// broadcast reads). Causal key-tile skipping; heavy q-tiles launch first.
// ---------------------------------------------------------------------------
__global__ void __launch_bounds__(256, 1) attn_kernel()
{
    extern __shared__ float sm[];
    float* Qt = sm;                           // [64][128]   (d-major)
    float* Kt = sm + 64 * 128;                // [64][128]   (d-major)
    float* Vs = sm + 2 * 64 * 128;            // [128][64]   (row-major)
    float* Ps = sm + 2 * 64 * 128 + 128 * 64; // [128][128]  (row-major)

    const int tid = threadIdx.x;
    const int tx = tid & 15;
    const int ty = tid >> 4;
    const int r0 = ty * 8;                    // q rows owned
    const int c0 = tx * 8;                    // k cols owned (S phase)

    const int qt = 15 - (int)blockIdx.x;      // heavy tiles first
    const int bh = blockIdx.y;
    const int q0 = qt * 128;

    const float* Qg = g_Q + (bh * T_ + q0) * HD_;
    const float* Kg = g_K + bh * T_ * HD_;
    const float* Vg = g_V + bh * T_ * HD_;

    // Load Q tile transposed (Qt[d][q]); STS conflict-free (lanes -> rows)
#pragma unroll
    for (int it = 0; it < 8; it++) {
        int gi = it * 256 + tid;
        int row = gi & 127;
        int cc = (gi >> 7) * 4;
        float4 v = *(const float4*)(Qg + row * HD_ + cc);
        Qt[(cc + 0) * 128 + row] = v.x;
        Qt[(cc + 1) * 128 + row] = v.y;
        Qt[(cc + 2) * 128 + row] = v.z;
        Qt[(cc + 3) * 128 + row] = v.w;
    }

    float O[8][4];
    float m_i[8], l_i[8];
#pragma unroll
    for (int i = 0; i < 8; i++) {
        m_i[i] = -1e30f;
        l_i[i] = 0.f;
        O[i][0] = O[i][1] = O[i][2] = O[i][3] = 0.f;
    }

    for (int kt = 0; kt <= qt; kt++) {
        const int k0 = kt * 128;
        __syncthreads();   // protect Kt/Vs/Ps from previous iteration readers
#pragma unroll
        for (int it = 0; it < 8; it++) {
            int gi = it * 256 + tid;
            int row = gi & 127;
            int cc = (gi >> 7) * 4;
            float4 v = *(const float4*)(Kg + (k0 + row) * HD_ + cc);
            Kt[(cc + 0) * 128 + row] = v.x;
            Kt[(cc + 1) * 128 + row] = v.y;
            Kt[(cc + 2) * 128 + row] = v.z;
            Kt[(cc + 3) * 128 + row] = v.w;
            int vr = gi >> 4;
            int vc = (gi & 15) * 4;
            *(float4*)&Vs[vr * 64 + vc] = *(const float4*)(Vg + (k0 + vr) * HD_ + vc);
        }
        __syncthreads();

        // S = Q @ K^T (already scaled via Q)
        float acc[8][8];
#pragma unroll
        for (int i = 0; i < 8; i++)
#pragma unroll
            for (int j = 0; j < 8; j++) acc[i][j] = 0.f;

#pragma unroll 8
        for (int kk = 0; kk < 64; kk++) {
            float qf[8], kf[8];
            *(float4*)(qf)     = *(const float4*)&Qt[kk * 128 + r0];
            *(float4*)(qf + 4) = *(const float4*)&Qt[kk * 128 + r0 + 4];
            *(float4*)(kf)     = *(const float4*)&Kt[kk * 128 + c0];
            *(float4*)(kf + 4) = *(const float4*)&Kt[kk * 128 + c0 + 4];
#pragma unroll
            for (int i = 0; i < 8; i++)
#pragma unroll
                for (int j = 0; j < 8; j++)
                    acc[i][j] = fmaf(qf[i], kf[j], acc[i][j]);
        }

        if (kt == qt) {   // only the diagonal tile is partially masked
#pragma unroll
            for (int i = 0; i < 8; i++)
#pragma unroll
                for (int j = 0; j < 8; j++)
                    if (c0 + j > r0 + i) acc[i][j] = -1e30f;
        }

        // online softmax update (row stats reduced across the 16 tx lanes)
#pragma unroll
        for (int i = 0; i < 8; i++) {
            float mx = acc[i][0];
#pragma unroll
            for (int j = 1; j < 8; j++) mx = fmaxf(mx, acc[i][j]);
#pragma unroll
            for (int o = 8; o > 0; o >>= 1)
                mx = fmaxf(mx, __shfl_xor_sync(0xffffffffu, mx, o, 16));
            const float m_new = fmaxf(m_i[i], mx);
            const float f = __expf(m_i[i] - m_new);
            m_i[i] = m_new;
            float rs = 0.f;
#pragma unroll
            for (int j = 0; j < 8; j++) {
                acc[i][j] = __expf(acc[i][j] - m_new);
                rs += acc[i][j];
            }
#pragma unroll
            for (int o = 8; o > 0; o >>= 1)
                rs += __shfl_xor_sync(0xffffffffu, rs, o, 16);
            l_i[i] = l_i[i] * f + rs;
            O[i][0] *= f; O[i][1] *= f; O[i][2] *= f; O[i][3] *= f;
            *(float4*)&Ps[(r0 + i) * 128 + c0] =
                make_float4(acc[i][0], acc[i][1], acc[i][2], acc[i][3]);
            *(float4*)&Ps[(r0 + i) * 128 + c0 + 4] =
                make_float4(acc[i][4], acc[i][5], acc[i][6], acc[i][7]);
        }
        __syncthreads();

        // O += P @ V  (thread owns q rows r0..r0+7, d cols tx*4..tx*4+3)
#pragma unroll 2
        for (int kk = 0; kk < 128; kk++) {
            float4 v = *(const float4*)&Vs[kk * 64 + tx * 4];
#pragma unroll
            for (int i = 0; i < 8; i++) {
                float p = Ps[(r0 + i) * 128 + kk];
                O[i][0] = fmaf(p, v.x, O[i][0]);
                O[i][1] = fmaf(p, v.y, O[i][1]);
                O[i][2] = fmaf(p, v.z, O[i][2]);
                O[i][3] = fmaf(p, v.w, O[i][3]);
            }
        }
    }

    // epilogue: normalize and write to [b*T+t][h*64+d]
    const int b = bh >> 4;
    const int h = bh & 15;
#pragma unroll
    for (int i = 0; i < 8; i++) {
        const float inv = 1.f / l_i[i];
        float* p = g_O + (b * T_ + q0 + r0 + i) * C_ + h * HD_ + tx * 4;
        *(float4*)p = make_float4(O[i][0] * inv, O[i][1] * inv,
                                  O[i][2] * inv, O[i][3] * inv);
    }
}

// ---------------------------------------------------------------------------
extern "C" void kernel_launch(void* const* d_in, const int* in_sizes, int n_in,
                              void* d_out, int out_size)
{
    const float* x     = (const float*)d_in[0];
    const float* cosb  = (const float*)d_in[1];
    const float* sinb  = (const float*)d_in[2];
    const float* w_qkv = (const float*)d_in[3];
    const float* w_out = (const float*)d_in[4];
    float* out = (float*)d_out;

    (void)in_sizes; (void)n_in; (void)out_size;

    cudaFuncSetAttribute(attn_kernel,
                         cudaFuncAttributeMaxDynamicSharedMemorySize, 163840);

    // 1) QKV projection: [4096,1024] @ [3072,1024]^T, scatter to Q/K/V
    gemm_kernel<0><<<dim3(24, 32), 256>>>(x, w_qkv, nullptr);
    // 2) RoPE on Q and K (folds 1/sqrt(64) into Q)
    rope_kernel<<<8192, 256>>>(cosb, sinb);
    // 3) causal flash attention -> g_O [4096,1024]
    attn_kernel<<<dim3(16, 32), 256, 163840>>>();
    // 4) output projection: g_O @ [1024,1024]^T -> d_out
    gemm_kernel<1><<<dim3(8, 32), 256>>>(nullptr, w_out, out);
}

// round 8
// speedup vs baseline: 1.0017x; 1.0017x over previous
#include <cuda_runtime.h>

#define B_   2
#define T_   2048
#define C_   1024
#define NH_  16
#define HD_  64
#define NTOK 4096   // B_*T_

// Scratch (allocation-free: __device__ globals)
__device__ float g_Q[B_ * NH_ * T_ * HD_];   // [b][h][t][d]
__device__ float g_K[B_ * NH_ * T_ * HD_];
__device__ float g_V[B_ * NH_ * T_ * HD_];
__device__ float g_O[NTOK * C_];             // attention out, [b*T+t][h*64+d]

// ---------------------------------------------------------------------------
// GEMM: C[M,N] = A[M,K] @ W[N,K]^T   (K = 1024, tiles 128x128x8, 8x8/thread)
// MODE 0: A = x, scatter output into g_Q/g_K/g_V ([B,H,T,D])
// MODE 1: A = g_O, write Cout row-major (final output)
// ---------------------------------------------------------------------------
template <int MODE>
__global__ void __launch_bounds__(256, 2)
gemm_kernel(const float* __restrict__ A_in, const float* __restrict__ W,
            float* __restrict__ Cout)
{
    __shared__ float As[8][128];
    __shared__ float Bs[8][128];
    const float* A = (MODE == 1) ? (const float*)g_O : A_in;

    const int tid = threadIdx.x;
    const int tx = tid & 15;
    const int ty = tid >> 4;
    const int m0 = blockIdx.y * 128;
    const int n0 = blockIdx.x * 128;

    float acc[8][8];
#pragma unroll
    for (int i = 0; i < 8; i++)
#pragma unroll
        for (int j = 0; j < 8; j++) acc[i][j] = 0.f;

    const int lr = tid >> 1;          // 0..127
    const int lc = (tid & 1) * 4;     // 0 or 4
    const float* Ag = A + (m0 + lr) * 1024 + lc;
    const float* Wg = W + (n0 + lr) * 1024 + lc;

    for (int k0 = 0; k0 < 1024; k0 += 8) {
        float4 a = *(const float4*)(Ag + k0);
        float4 b = *(const float4*)(Wg + k0);
        __syncthreads();
        As[lc + 0][lr] = a.x; As[lc + 1][lr] = a.y;
        As[lc + 2][lr] = a.z; As[lc + 3][lr] = a.w;
        Bs[lc + 0][lr] = b.x; Bs[lc + 1][lr] = b.y;
        Bs[lc + 2][lr] = b.z; Bs[lc + 3][lr] = b.w;
        __syncthreads();
#pragma unroll
        for (int kk = 0; kk < 8; kk++) {
            float af[8], bf[8];
            *(float4*)(af)     = *(const float4*)&As[kk][ty * 8];
            *(float4*)(af + 4) = *(const float4*)&As[kk][ty * 8 + 4];
            *(float4*)(bf)     = *(const float4*)&Bs[kk][tx * 8];
            *(float4*)(bf + 4) = *(const float4*)&Bs[kk][tx * 8 + 4];
#pragma unroll
            for (int i = 0; i < 8; i++)
#pragma unroll
                for (int j = 0; j < 8; j++)
                    acc[i][j] = fmaf(af[i], bf[j], acc[i][j]);
        }
    }

    if (MODE == 0) {
        // scatter into Q/K/V [b][h][t][d]; column block lies in one head (64|8)
        const int ncol = n0 + tx * 8;
        const int part = ncol >> 10;            // 0=Q 1=K 2=V
        const int h    = (ncol >> 6) & 15;
        const int d0   = ncol & 63;
        float* dst = (part == 0) ? g_Q : (part == 1) ? g_K : g_V;
#pragma unroll
        for (int i = 0; i < 8; i++) {
            const int m = m0 + ty * 8 + i;
            const int b = m >> 11;
            const int t = m & 2047;
            float* p = dst + (((b * NH_ + h) * T_) + t) * HD_ + d0;
            *(float4*)p       = make_float4(acc[i][0], acc[i][1], acc[i][2], acc[i][3]);
            *(float4*)(p + 4) = make_float4(acc[i][4], acc[i][5], acc[i][6], acc[i][7]);
        }
    } else {
#pragma unroll
        for (int i = 0; i < 8; i++) {
            float* p = Cout + (m0 + ty * 8 + i) * 1024 + n0 + tx * 8;
            *(float4*)p       = make_float4(acc[i][0], acc[i][1], acc[i][2], acc[i][3]);
            *(float4*)(p + 4) = make_float4(acc[i][4], acc[i][5], acc[i][6], acc[i][7]);
        }
    }
}

// ---------------------------------------------------------------------------
// RoPE (in place on g_Q/g_K); folds softmax scale 1/sqrt(64) into Q.
// One thread per (b,h,t,d<32) rotation pair, handles both Q and K.
// ---------------------------------------------------------------------------
__global__ void rope_kernel(const float* __restrict__ cosb,
                            const float* __restrict__ sinb)
{
    const int idx = blockIdx.x * blockDim.x + threadIdx.x;
    if (idx >= B_ * NH_ * T_ * 32) return;
    const int d  = idx & 31;
    const int t  = (idx >> 5) & 2047;
    const int bh = idx >> 16;                  // /(2048*32)
    const float c = cosb[t * 32 + d];
    const float s = sinb[t * 32 + d];
    const int base = (bh * T_ + t) * HD_ + d;

    const float q1 = g_Q[base], q2 = g_Q[base + 32];
    g_Q[base]      = (q1 * c - q2 * s) * 0.125f;
    g_Q[base + 32] = (q1 * s + q2 * c) * 0.125f;

    const float k1 = g_K[base], k2 = g_K[base + 32];
    g_K[base]      = k1 * c - k2 * s;
    g_K[base + 32] = k1 * s + k2 * c;
}

// ---------------------------------------------------------------------------
// Flash attention, fp32, causal. Tile: 128 q x 128 k, 256 threads (16x16),
// 8x8 S accum per thread, 8x4 O accum per thread. Q/K stored d-major in smem
// (GEMM-style conflict-free fragment reads); P row-major (float4 writes,
// broadcast reads). Causal key-tile skipping; heavy q-tiles launch first.
// ---------------------------------------------------------------------------
__global__ void __launch_bounds__(256, 1) attn_kernel()
{
    extern __shared__ float sm[];
    float* Qt = sm;                           // [64][128]   (d-major)
    float* Kt = sm + 64 * 128;                // [64][128]   (d-major)
    float* Vs = sm + 2 * 64 * 128;            // [128][64]   (row-major)
    float* Ps = sm + 2 * 64 * 128 + 128 * 64; // [128][128]  (row-major)

    const int tid = threadIdx.x;
    const int tx = tid & 15;
    const int ty = tid >> 4;
    const int r0 = ty * 8;                    // q rows owned
    const int c0 = tx * 8;                    // k cols owned (S phase)

    const int qt = 15 - (int)blockIdx.x;      // heavy tiles first
    const int bh = blockIdx.y;
    const int q0 = qt * 128;

    const float* Qg = g_Q + (bh * T_ + q0) * HD_;
    const float* Kg = g_K + bh * T_ * HD_;
    const float* Vg = g_V + bh * T_ * HD_;

    // Load Q tile transposed (Qt[d][q]); STS conflict-free (lanes -> rows)
#pragma unroll
    for (int it = 0; it < 8; it++) {
        int gi = it * 256 + tid;
        int row = gi & 127;
        int cc = (gi >> 7) * 4;
        float4 v = *(const float4*)(Qg + row * HD_ + cc);
        Qt[(cc + 0) * 128 + row] = v.x;
        Qt[(cc + 1) * 128 + row] = v.y;
        Qt[(cc + 2) * 128 + row] = v.z;
        Qt[(cc + 3) * 128 + row] = v.w;
    }

    float O[8][4];
    float m_i[8], l_i[8];
#pragma unroll
    for (int i = 0; i < 8; i++) {
        m_i[i] = -1e30f;
        l_i[i] = 0.f;
        O[i][0] = O[i][1] = O[i][2] = O[i][3] = 0.f;
    }

    for (int kt = 0; kt <= qt; kt++) {
        const int k0 = kt * 128;
        __syncthreads();   // protect Kt/Vs/Ps from previous iteration readers
#pragma unroll
        for (int it = 0; it < 8; it++) {
            int gi = it * 256 + tid;
            int row = gi & 127;
            int cc = (gi >> 7) * 4;
            float4 v = *(const float4*)(Kg + (k0 + row) * HD_ + cc);
            Kt[(cc + 0) * 128 + row] = v.x;
            Kt[(cc + 1) * 128 + row] = v.y;
            Kt[(cc + 2) * 128 + row] = v.z;
            Kt[(cc + 3) * 128 + row] = v.w;
            int vr = gi >> 4;
            int vc = (gi & 15) * 4;
            *(float4*)&Vs[vr * 64 + vc] = *(const float4*)(Vg + (k0 + vr) * HD_ + vc);
        }
        __syncthreads();

        // S = Q @ K^T (already scaled via Q)
        float acc[8][8];
#pragma unroll
        for (int i = 0; i < 8; i++)
#pragma unroll
            for (int j = 0; j < 8; j++) acc[i][j] = 0.f;

#pragma unroll 8
        for (int kk = 0; kk < 64; kk++) {
            float qf[8], kf[8];
            *(float4*)(qf)     = *(const float4*)&Qt[kk * 128 + r0];
            *(float4*)(qf + 4) = *(const float4*)&Qt[kk * 128 + r0 + 4];
            *(float4*)(kf)     = *(const float4*)&Kt[kk * 128 + c0];
            *(float4*)(kf + 4) = *(const float4*)&Kt[kk * 128 + c0 + 4];
#pragma unroll
            for (int i = 0; i < 8; i++)
#pragma unroll
                for (int j = 0; j < 8; j++)
                    acc[i][j] = fmaf(qf[i], kf[j], acc[i][j]);
        }

        if (kt == qt) {   // only the diagonal tile is partially masked
#pragma unroll
            for (int i = 0; i < 8; i++)
#pragma unroll
                for (int j = 0; j < 8; j++)
                    if (c0 + j > r0 + i) acc[i][j] = -1e30f;
        }

        // online softmax update (row stats reduced across the 16 tx lanes)
#pragma unroll
        for (int i = 0; i < 8; i++) {
            float mx = acc[i][0];
#pragma unroll
            for (int j = 1; j < 8; j++) mx = fmaxf(mx, acc[i][j]);
#pragma unroll
            for (int o = 8; o > 0; o >>= 1)
                mx = fmaxf(mx, __shfl_xor_sync(0xffffffffu, mx, o, 16));
            const float m_new = fmaxf(m_i[i], mx);
            const float f = __expf(m_i[i] - m_new);
            m_i[i] = m_new;
            float rs = 0.f;
#pragma unroll
            for (int j = 0; j < 8; j++) {
                acc[i][j] = __expf(acc[i][j] - m_new);
                rs += acc[i][j];
            }
#pragma unroll
            for (int o = 8; o > 0; o >>= 1)
                rs += __shfl_xor_sync(0xffffffffu, rs, o, 16);
            l_i[i] = l_i[i] * f + rs;
            O[i][0] *= f; O[i][1] *= f; O[i][2] *= f; O[i][3] *= f;
            *(float4*)&Ps[(r0 + i) * 128 + c0] =
                make_float4(acc[i][0], acc[i][1], acc[i][2], acc[i][3]);
            *(float4*)&Ps[(r0 + i) * 128 + c0 + 4] =
                make_float4(acc[i][4], acc[i][5], acc[i][6], acc[i][7]);
        }
        __syncthreads();

        // O += P @ V  (thread owns q rows r0..r0+7, d cols tx*4..tx*4+3)
#pragma unroll 2
        for (int kk = 0; kk < 128; kk++) {
            float4 v = *(const float4*)&Vs[kk * 64 + tx * 4];
#pragma unroll
            for (int i = 0; i < 8; i++) {
                float p = Ps[(r0 + i) * 128 + kk];
                O[i][0] = fmaf(p, v.x, O[i][0]);
                O[i][1] = fmaf(p, v.y, O[i][1]);
                O[i][2] = fmaf(p, v.z, O[i][2]);
                O[i][3] = fmaf(p, v.w, O[i][3]);
            }
        }
    }

    // epilogue: normalize and write to [b*T+t][h*64+d]
    const int b = bh >> 4;
    const int h = bh & 15;
#pragma unroll
    for (int i = 0; i < 8; i++) {
        const float inv = 1.f / l_i[i];
        float* p = g_O + (b * T_ + q0 + r0 + i) * C_ + h * HD_ + tx * 4;
        *(float4*)p = make_float4(O[i][0] * inv, O[i][1] * inv,
                                  O[i][2] * inv, O[i][3] * inv);
    }
}

// ---------------------------------------------------------------------------
extern "C" void kernel_launch(void* const* d_in, const int* in_sizes, int n_in,
                              void* d_out, int out_size)
{
    const float* x     = (const float*)d_in[0];
    const float* cosb  = (const float*)d_in[1];
    const float* sinb  = (const float*)d_in[2];
    const float* w_qkv = (const float*)d_in[3];
    const float* w_out = (const float*)d_in[4];
    float* out = (float*)d_out;

    (void)in_sizes; (void)n_in; (void)out_size;

    cudaFuncSetAttribute(attn_kernel,
                         cudaFuncAttributeMaxDynamicSharedMemorySize, 163840);

    // 1) QKV projection: [4096,1024] @ [3072,1024]^T, scatter to Q/K/V
    gemm_kernel<0><<<dim3(24, 32), 256>>>(x, w_qkv, nullptr);
    // 2) RoPE on Q and K (folds 1/sqrt(64) into Q)
    rope_kernel<<<8192, 256>>>(cosb, sinb);
    // 3) causal flash attention -> g_O [4096,1024]
    attn_kernel<<<dim3(16, 32), 256, 163840>>>();
    // 4) output projection: g_O @ [1024,1024]^T -> d_out
    gemm_kernel<1><<<dim3(8, 32), 256>>>(nullptr, w_out, out);
}